// round 10
// baseline (speedup 1.0000x reference)
#include <cuda_runtime.h>

#define SDIM   128
#define VDIM   352           // 64*3 + 32*5
#define DIM    480
#define RPB    4             // rows per chunk
#define NTHR   128
#define NVTOT  (RPB * 88)    // 352 float4 in vector region per chunk
#define EPS    1e-5f

__device__ __forceinline__ float4 ldcs_f4(const float4* p) {
    float4 v;
    asm volatile("ld.global.cs.v4.f32 {%0,%1,%2,%3}, [%4];"
                 : "=f"(v.x), "=f"(v.y), "=f"(v.z), "=f"(v.w) : "l"(p));
    return v;
}
__device__ __forceinline__ void stcs_f4(float4* p, float4 v) {
    asm volatile("st.global.cs.v4.f32 [%0], {%1,%2,%3,%4};"
                 :: "l"(p), "f"(v.x), "f"(v.y), "f"(v.z), "f"(v.w));
}

__device__ __forceinline__ void load_chunk(
    const float* __restrict__ x, long long row0,
    int tid, int lane, int wrp, float4& sv, float4 v[3])
{
    sv = ldcs_f4((const float4*)(x + (row0 + wrp) * DIM) + lane);
    #pragma unroll
    for (int k = 0; k < 3; k++) {
        int idx = tid + NTHR * k;
        if (idx < NVTOT) {
            int r = idx / 88, j = idx - r * 88;
            v[k] = ldcs_f4((const float4*)(x + (row0 + r) * DIM + SDIM) + j);
        }
    }
}

__global__ __launch_bounds__(NTHR) void eln_kernel(
    const float* __restrict__ x,
    const float* __restrict__ weight,
    const float* __restrict__ bias,
    float* __restrict__ out,
    int nChunks)
{
    __shared__ float vec[RPB][VDIM];   // 5.6 KB

    const int tid  = threadIdx.x;
    const int lane = tid & 31;
    const int wrp  = tid >> 5;
    const int stride = gridDim.x;

    const float4 w4 = __ldg((const float4*)weight + lane);
    const float4 b4 = __ldg((const float4*)bias   + lane);

    long long c = blockIdx.x;
    float4 sv, v[3];
    if (c < nChunks) load_chunk(x, c * RPB, tid, lane, wrp, sv, v);

    while (c < nChunks) {
        // ---- prefetch next chunk's loads (overlap with compute+stores) ----
        const long long cn = c + stride;
        float4 svn, vn[3];
        if (cn < nChunks) load_chunk(x, cn * RPB, tid, lane, wrp, svn, vn);

        const long long row0 = c * RPB;

        // ---- scalar layernorm: warp-local, no barrier ----
        float sum = sv.x + sv.y + sv.z + sv.w;
        float sq  = sv.x * sv.x + sv.y * sv.y + sv.z * sv.z + sv.w * sv.w;
        #pragma unroll
        for (int o = 16; o; o >>= 1) {
            sum += __shfl_xor_sync(0xFFFFFFFFu, sum, o);
            sq  += __shfl_xor_sync(0xFFFFFFFFu, sq,  o);
        }
        const float m  = sum * (1.0f / 128.0f);
        const float rs = rsqrtf(sq * (1.0f / 128.0f) - m * m + EPS);
        float4 so;
        so.x = (sv.x - m) * rs * w4.x + b4.x;
        so.y = (sv.y - m) * rs * w4.y + b4.y;
        so.z = (sv.z - m) * rs * w4.z + b4.z;
        so.w = (sv.w - m) * rs * w4.w + b4.w;
        stcs_f4((float4*)(out + (row0 + wrp) * DIM) + lane, so);

        // ---- stage vector region into smem ----
        #pragma unroll
        for (int k = 0; k < 3; k++) {
            int idx = tid + NTHR * k;
            if (idx < NVTOT) ((float4*)vec)[idx] = v[k];
        }
        __syncthreads();

        // ---- segment norms: 4 rows x 96 segments = 384, 3/thread ----
        #pragma unroll
        for (int k = 0; k < 3; k++) {
            int s = tid + NTHR * k;       // 0..383
            int r = s / 96, k96 = s - r * 96;
            if (k96 < 64) {
                float* p = &vec[r][3 * k96];
                float a = p[0], b = p[1], cc = p[2];
                float sm = (a + b + cc) * (1.0f / 3.0f);
                float da = a - sm, db = b - sm, dc = cc - sm;
                float rr = rsqrtf((da * da + db * db + dc * dc) * (1.0f / 3.0f) + EPS);
                p[0] = da * rr; p[1] = db * rr; p[2] = dc * rr;
            } else {
                float* p = &vec[r][192 + 5 * (k96 - 64)];
                float a = p[0], b = p[1], cc = p[2], d = p[3], e = p[4];
                float sm = (a + b + cc + d + e) * 0.2f;
                float da = a - sm, db = b - sm, dc = cc - sm, dd = d - sm, de = e - sm;
                float rr = rsqrtf((da * da + db * db + dc * dc + dd * dd + de * de) * 0.2f + EPS);
                p[0] = da * rr; p[1] = db * rr; p[2] = dc * rr; p[3] = dd * rr; p[4] = de * rr;
            }
        }
        __syncthreads();

        // ---- vector region stores ----
        #pragma unroll
        for (int k = 0; k < 3; k++) {
            int idx = tid + NTHR * k;
            if (idx < NVTOT) {
                int r = idx / 88, j = idx - r * 88;
                stcs_f4((float4*)(out + (row0 + r) * DIM + SDIM) + j, ((float4*)vec)[idx]);
            }
        }

        // ---- rotate pipeline ----
        sv = svn; v[0] = vn[0]; v[1] = vn[1]; v[2] = vn[2];
        c = cn;
    }
}

extern "C" void kernel_launch(void* const* d_in, const int* in_sizes, int n_in,
                              void* d_out, int out_size)
{
    const float* x      = (const float*)d_in[0];
    const float* weight = (const float*)d_in[1];
    const float* bias   = (const float*)d_in[2];
    float* out = (float*)d_out;

    const int n_rows  = in_sizes[0] / DIM;   // 262144
    const int nChunks = n_rows / RPB;        // 65536
    const int grid    = 148 * 8;             // persistent CTAs, ~55 chunks each
    eln_kernel<<<grid, NTHR>>>(x, weight, bias, out, nChunks);
}